// round 1
// baseline (speedup 1.0000x reference)
#include <cuda_runtime.h>
#include <math.h>

#define W 512
#define H 512
#define HW (H * W)
#define TWO_PI 6.283185307179586f
#define ALPHA_THRESH (1.0f / 255.0f)

__global__ void splat_kernel(const float* __restrict__ xyz,
                             const float* __restrict__ scaling,
                             const float* __restrict__ rot,
                             const float* __restrict__ feat,
                             const float* __restrict__ opac,
                             float* __restrict__ out,
                             int n) {
    int gwarp = (blockIdx.x * blockDim.x + threadIdx.x) >> 5;
    int lane = threadIdx.x & 31;
    if (gwarp >= n) return;
    int g = gwarp;

    // Per-Gaussian prep (all lanes compute redundantly; loads broadcast via L1)
    float mx = tanhf(xyz[2 * g]);
    float my = tanhf(xyz[2 * g + 1]);
    float sx = fabsf(scaling[2 * g] + 0.5f);
    float sy = fabsf(scaling[2 * g + 1] + 0.5f);
    float theta = (1.0f / (1.0f + expf(-rot[g]))) * TWO_PI;

    float cx = 0.5f * ((mx + 1.0f) * (float)W - 1.0f);
    float cy = 0.5f * ((my + 1.0f) * (float)H - 1.0f);

    float sth, cth;
    sincosf(theta, &sth, &cth);
    float sx2 = sx * sx;
    float sy2 = sy * sy;
    float a = cth * cth * sx2 + sth * sth * sy2;   // covariance xx
    float b = cth * sth * (sx2 - sy2);
    float c = sth * sth * sx2 + cth * cth * sy2;   // covariance yy
    float det = a * c - b * b;
    if (!(det > 0.0f)) return;                     // valid gate
    float inv_det = 1.0f / fmaxf(det, 1e-12f);
    float A = c * inv_det;                          // conic (inverse covariance)
    float B = -b * inv_det;
    float C = a * inv_det;

    float op = opac[g];
    // alpha = op * exp(-sigma) > 1/255  <=>  sigma < ln(255*op)
    float tmax = logf(op * 255.0f);
    if (!(tmax > 0.0f)) return;

    // bbox half-extents from conic level set: dx_max = sqrt(2*tmax*Sigma_xx)
    float rx = sqrtf(2.0f * tmax * a) + 1.0f;      // +1 margin; exact test re-rejects
    float ry = sqrtf(2.0f * tmax * c) + 1.0f;

    int x0 = max(0, (int)ceilf(cx - rx));
    int x1 = min(W - 1, (int)floorf(cx + rx));
    int y0 = max(0, (int)ceilf(cy - ry));
    int y1 = min(H - 1, (int)floorf(cy + ry));
    if (x1 < x0 || y1 < y0) return;

    int bw = x1 - x0 + 1;
    int bh = y1 - y0 + 1;
    int npix = bw * bh;

    float c0 = feat[3 * g];
    float c1 = feat[3 * g + 1];
    float c2 = feat[3 * g + 2];

    for (int i = lane; i < npix; i += 32) {
        int px = x0 + i % bw;
        int py = y0 + i / bw;
        float dx = cx - (float)px;
        float dy = cy - (float)py;
        float sigma = 0.5f * (A * dx * dx + C * dy * dy) + B * dx * dy;
        if (sigma < 0.0f) continue;
        float alpha = op * __expf(-sigma);
        if (alpha > ALPHA_THRESH) {
            int pix = py * W + px;
            atomicAdd(&out[pix], alpha * c0);
            atomicAdd(&out[HW + pix], alpha * c1);
            atomicAdd(&out[2 * HW + pix], alpha * c2);
        }
    }
}

__global__ void clip_kernel(float* __restrict__ out, int n4) {
    int i = blockIdx.x * blockDim.x + threadIdx.x;
    if (i >= n4) return;
    float4 v = ((float4*)out)[i];
    v.x = fminf(fmaxf(v.x, 0.0f), 1.0f);
    v.y = fminf(fmaxf(v.y, 0.0f), 1.0f);
    v.z = fminf(fmaxf(v.z, 0.0f), 1.0f);
    v.w = fminf(fmaxf(v.w, 0.0f), 1.0f);
    ((float4*)out)[i] = v;
}

extern "C" void kernel_launch(void* const* d_in, const int* in_sizes, int n_in,
                              void* d_out, int out_size) {
    const float* xyz     = (const float*)d_in[0];  // (N,2)
    const float* scaling = (const float*)d_in[1];  // (N,2)
    const float* rot     = (const float*)d_in[2];  // (N,1)
    const float* feat    = (const float*)d_in[3];  // (N,3)
    const float* opac    = (const float*)d_in[4];  // (N,1)
    float* out = (float*)d_out;                     // (1,3,512,512)

    int n = in_sizes[0] / 2;

    cudaMemsetAsync(d_out, 0, (size_t)out_size * sizeof(float));

    int threads = 256;                 // 8 warps -> 8 gaussians per block
    int blocks = (n * 32 + threads - 1) / threads;
    splat_kernel<<<blocks, threads>>>(xyz, scaling, rot, feat, opac, out, n);

    int n4 = out_size / 4;
    clip_kernel<<<(n4 + 255) / 256, 256>>>(out, n4);
}